// round 14
// baseline (speedup 1.0000x reference)
#include <cuda_runtime.h>
#include <cuda_bf16.h>
#include <cstdint>

#define NN 50000
#define NE 600000
#define DD 128
#define DE 32

typedef unsigned long long u64;

// Scratch (device globals — no allocation allowed)
__device__ float g_agg[NN * DD];
__device__ float g_h[NN * DD];
__device__ float g_t[NN * DD];
__device__ int   g_rowptr[NN + 1];
__device__ int   g_woff[NN];
__device__ int   g_cnt[NN];
__device__ int   g_srcp[NE];
__device__ int   g_dstp[NE];
// pre-converted operands
__device__ __nv_bfloat16 g_eaH[(size_t)NE * DE];   // permuted edge_attr hi
__device__ __nv_bfloat16 g_eaL[(size_t)NE * DE];   // permuted edge_attr lo
__device__ __nv_bfloat16 g_wtH[6][DD * DD];        // node W transposed [n][k] hi
__device__ __nv_bfloat16 g_wtL[6][DD * DD];
__device__ __nv_bfloat16 g_weH[2][DD * DE];        // edge we transposed [n][k] hi
__device__ __nv_bfloat16 g_weL[2][DD * DE];

// ---- helpers ----
static __device__ __forceinline__ uint32_t smem_u32(const void* p) {
    uint32_t a;
    asm("{ .reg .u64 t; cvta.to.shared.u64 t, %1; cvt.u32.u64 %0, t; }" : "=r"(a) : "l"(p));
    return a;
}
static __device__ __forceinline__ uint32_t packbf(float a, float b) {
    __nv_bfloat16 ha = __float2bfloat16_rn(a), hb = __float2bfloat16_rn(b);
    uint16_t ua = *(uint16_t*)&ha, ub = *(uint16_t*)&hb;
    return (uint32_t)ua | ((uint32_t)ub << 16);
}
static __device__ __forceinline__ float bflo(float a) {
    __nv_bfloat16 h = __float2bfloat16_rn(a);
    return a - __bfloat162float(h);
}
// swizzled byte addr: 256B rows (128 bf16), chunk c in 0..15
static __device__ __forceinline__ uint32_t asw(int row, int c) {
    return (uint32_t)(row * 256 + ((c ^ (row & 7)) << 4));
}
// swizzled byte addr: 128B rows (64 bf16 = hi32|lo32), chunk c in 0..7
static __device__ __forceinline__ uint32_t asw128(int row, int c) {
    return (uint32_t)(row * 128 + ((c ^ (row & 7)) << 4));
}

#define LDSM_X4(r, a) \
    asm volatile("ldmatrix.sync.aligned.m8n8.x4.shared.b16 {%0,%1,%2,%3}, [%4];" \
        : "=r"((r)[0]), "=r"((r)[1]), "=r"((r)[2]), "=r"((r)[3]) : "r"(a))

__device__ __forceinline__ void mma16816(float* c, const uint32_t* a, uint32_t b0, uint32_t b1) {
    asm volatile("mma.sync.aligned.m16n8k16.row.col.f32.bf16.bf16.f32 "
        "{%0,%1,%2,%3}, {%4,%5,%6,%7}, {%8,%9}, {%0,%1,%2,%3};"
        : "+f"(c[0]), "+f"(c[1]), "+f"(c[2]), "+f"(c[3])
        : "r"(a[0]), "r"(a[1]), "r"(a[2]), "r"(a[3]), "r"(b0), "r"(b1));
}

// ===========================================================================
// prep kernel: all weight conversions + zero g_cnt, one launch.
// work layout: [0,24576) node W (6 x 4096), [24576,26624) edge we (2 x 1024),
//              [26624, 26624+NN) zero cnt
// ===========================================================================
__global__ void prep_kernel(const float* __restrict__ w0, const float* __restrict__ w1,
                            const float* __restrict__ w2, const float* __restrict__ w3,
                            const float* __restrict__ w4, const float* __restrict__ w5,
                            const float* __restrict__ we0, const float* __restrict__ we1) {
    int gid = blockIdx.x * blockDim.x + threadIdx.x;
    if (gid < 24576) {
        int wi = gid >> 12;          // 0..5
        int idx = gid & 4095;
        const float* W = (wi == 0) ? w0 : (wi == 1) ? w1 : (wi == 2) ? w2
                       : (wi == 3) ? w3 : (wi == 4) ? w4 : w5;
        int n = idx & 127;
        int kq = idx >> 7;           // 0..31
        float v0 = W[(kq * 4 + 0) * 128 + n];
        float v1 = W[(kq * 4 + 1) * 128 + n];
        float v2 = W[(kq * 4 + 2) * 128 + n];
        float v3 = W[(kq * 4 + 3) * 128 + n];
        *(uint2*)(&g_wtH[wi][n * 128 + kq * 4]) = make_uint2(packbf(v0, v1), packbf(v2, v3));
        *(uint2*)(&g_wtL[wi][n * 128 + kq * 4]) =
            make_uint2(packbf(bflo(v0), bflo(v1)), packbf(bflo(v2), bflo(v3)));
    } else if (gid < 26624) {
        int q = gid - 24576;
        int wi = q >> 10;            // 0..1
        int idx = q & 1023;
        const float* W = wi ? we1 : we0;
        int n = idx & 127;
        int kq = idx >> 7;           // 0..7
        float v0 = W[(kq * 4 + 0) * 128 + n];
        float v1 = W[(kq * 4 + 1) * 128 + n];
        float v2 = W[(kq * 4 + 2) * 128 + n];
        float v3 = W[(kq * 4 + 3) * 128 + n];
        *(uint2*)(&g_weH[wi][n * 32 + kq * 4]) = make_uint2(packbf(v0, v1), packbf(v2, v3));
        *(uint2*)(&g_weL[wi][n * 32 + kq * 4]) =
            make_uint2(packbf(bflo(v0), bflo(v1)), packbf(bflo(v2), bflo(v3)));
    } else {
        int n = gid - 26624;
        if (n < NN) g_cnt[n] = 0;
    }
}

// ===========================================================================
// CSR build
// ===========================================================================
__global__ void hist_kernel(const int* __restrict__ ei) {
    int i = blockIdx.x * blockDim.x + threadIdx.x;
    if (i < NE) atomicAdd(&g_cnt[ei[NE + i]], 1);
}

__global__ void scan_kernel() {
    __shared__ int s[1024];
    const int tid = threadIdx.x;
    const int CH = (NN + 1023) / 1024;
    const int base = tid * CH;
    const int end = min(base + CH, NN);
    int tot = 0;
    for (int i = base; i < end; i++) tot += g_cnt[i];
    s[tid] = tot;
    __syncthreads();
#pragma unroll
    for (int off = 1; off < 1024; off <<= 1) {
        int t = (tid >= off) ? s[tid - off] : 0;
        __syncthreads();
        s[tid] += t;
        __syncthreads();
    }
    int run = s[tid] - tot;
    for (int i = base; i < end; i++) {
        int v = g_cnt[i];
        g_rowptr[i] = run;
        g_woff[i] = run;
        run += v;
    }
    if (end == NN) g_rowptr[NN] = run;
}

// scatter + edge_attr conversion fused: thread i places edge i at slot p
// and writes its bf16 hi/lo attr row directly to position p.
__global__ void scatter_conv_kernel(const int* __restrict__ ei, const float4* __restrict__ ea4) {
    int i = blockIdx.x * blockDim.x + threadIdx.x;
    if (i < NE) {
        int d = ei[NE + i];
        int p = atomicAdd(&g_woff[d], 1);
        g_srcp[p] = ei[i];
        g_dstp[p] = d;
#pragma unroll
        for (int c = 0; c < 4; c++) {
            float4 v0 = ea4[(long long)i * 8 + c * 2];
            float4 v1 = ea4[(long long)i * 8 + c * 2 + 1];
            uint4 hi = make_uint4(packbf(v0.x, v0.y), packbf(v0.z, v0.w),
                                  packbf(v1.x, v1.y), packbf(v1.z, v1.w));
            uint4 lo = make_uint4(packbf(bflo(v0.x), bflo(v0.y)), packbf(bflo(v0.z), bflo(v0.w)),
                                  packbf(bflo(v1.x), bflo(v1.y)), packbf(bflo(v1.z), bflo(v1.w)));
            *(uint4*)((char*)g_eaH + (long long)p * 64 + c * 16) = hi;
            *(uint4*)((char*)g_eaL + (long long)p * 64 + c * 16) = lo;
        }
    }
}

__global__ void copy4_kernel(const float4* __restrict__ s, float4* __restrict__ d, int n4) {
    int i = blockIdx.x * blockDim.x + threadIdx.x;
    if (i < n4) d[i] = s[i];
}

// ===========================================================================
// Edge kernel (mma): emb = ea@we via bf16-split mma -> Msg smem;
// epilogue = segmented reduction (relu(emb+be+x[src]) summed per dst run).
// 256 threads, 8 warps; warp w -> m16 tile, all 128 n. Edges CSR-sorted.
// ===========================================================================
#define E_EA  0
#define E_WE  16384
#define E_MSG 32768
#define E_TOTAL (32768 + 128 * 528)      // 100352
#define MSG_STRIDE 132                   // floats; 528B rows

__global__ void __launch_bounds__(256, 2)
edge_fused_kernel(const float* __restrict__ xin,
                  const __nv_bfloat16* __restrict__ weH,
                  const __nv_bfloat16* __restrict__ weL,
                  const float* __restrict__ be,
                  float* __restrict__ agg) {
    extern __shared__ char smem[];
    const uint32_t sb = smem_u32(smem);
    float* MsgS = (float*)(smem + E_MSG);
    const int tid = threadIdx.x;
    const long long i0 = (long long)blockIdx.x * 128;

    // load Ea tile (hi|lo 128B rows, swizzled) + We tile
#pragma unroll
    for (int l = 0; l < 4; l++) {
        int idx = tid + l * 256;          // 0..1023 : Ea
        int r = idx >> 3;
        int c = idx & 7;
        long long gi = i0 + r;
        uint4 v = make_uint4(0, 0, 0, 0);
        if (gi < NE) {
            const char* src = (c < 4) ? ((const char*)g_eaH + gi * 64 + c * 16)
                                      : ((const char*)g_eaL + gi * 64 + (c - 4) * 16);
            v = *(const uint4*)src;
        }
        *(uint4*)(smem + E_EA + asw128(r, c)) = v;
        // We
        const char* ws = (c < 4) ? ((const char*)weH + r * 64 + c * 16)
                                 : ((const char*)weL + r * 64 + (c - 4) * 16);
        *(uint4*)(smem + E_WE + asw128(r, c)) = *(const uint4*)ws;
    }
    __syncthreads();

    // ---- mma: 8 warps, warp w -> rows [w*16, w*16+16), cols 0..127 ----
    {
        const int w = tid >> 5;
        const int lane = tid & 31;
        const int m0 = w * 16;
        const int ar = m0 + (lane & 15);
        const int ak = lane >> 4;
        const int br = (lane & 7) + ((lane >> 4) << 3);
        const int bk = (lane >> 3) & 1;

        float c[16][4];
#pragma unroll
        for (int j = 0; j < 16; j++)
#pragma unroll
            for (int q = 0; q < 4; q++) c[j][q] = 0.f;

#pragma unroll
        for (int s = 0; s < 2; s++) {
            uint32_t ah[4], al[4];
            LDSM_X4(ah, sb + E_EA + asw128(ar, 2 * s + ak));
            LDSM_X4(al, sb + E_EA + asw128(ar, 4 + 2 * s + ak));
#pragma unroll
            for (int jp = 0; jp < 8; jp++) {
                int nrow = jp * 16 + br;
                uint32_t bh[4], bl[4];
                LDSM_X4(bh, sb + E_WE + asw128(nrow, 2 * s + bk));
                LDSM_X4(bl, sb + E_WE + asw128(nrow, 4 + 2 * s + bk));
                mma16816(c[jp * 2],     ah, bh[0], bh[1]);
                mma16816(c[jp * 2],     ah, bl[0], bl[1]);
                mma16816(c[jp * 2],     al, bh[0], bh[1]);
                mma16816(c[jp * 2 + 1], ah, bh[2], bh[3]);
                mma16816(c[jp * 2 + 1], ah, bl[2], bl[3]);
                mma16816(c[jp * 2 + 1], al, bh[2], bh[3]);
            }
        }
        // park emb in Msg smem (row-major, padded rows)
        const int g = lane >> 2;
        const int tig = lane & 3;
#pragma unroll
        for (int j = 0; j < 16; j++) {
            int col = j * 8 + tig * 2;
            *(float2*)(MsgS + (m0 + g) * MSG_STRIDE + col)     = make_float2(c[j][0], c[j][1]);
            *(float2*)(MsgS + (m0 + g + 8) * MSG_STRIDE + col) = make_float2(c[j][2], c[j][3]);
        }
    }
    __syncthreads();

    // ---- epilogue: segmented reduction over dst runs (cols tx*4 and 64+tx*4) ----
    const int tx = tid & 15;
    const int ty = tid >> 4;
    float4 bvA = *(const float4*)(be + tx * 4);
    float4 bvB = *(const float4*)(be + 64 + tx * 4);
    float bvv[8] = {bvA.x, bvA.y, bvA.z, bvA.w, bvB.x, bvB.y, bvB.z, bvB.w};

    int d_cur = -1;
    float sum[8];
#pragma unroll
    for (int rr = 0; rr < 8; rr++) {
        long long gi = i0 + ty * 8 + rr;
        if (gi < NE) {
            int d = g_dstp[gi];
            int src = g_srcp[gi];
            int row = ty * 8 + rr;
            float4 oA = *(const float4*)(MsgS + row * MSG_STRIDE + tx * 4);
            float4 oB = *(const float4*)(MsgS + row * MSG_STRIDE + 64 + tx * 4);
            float o[8] = {oA.x, oA.y, oA.z, oA.w, oB.x, oB.y, oB.z, oB.w};
            float4 xA = ((const float4*)xin)[(long long)src * 32 + tx];
            float4 xB = ((const float4*)xin)[(long long)src * 32 + 16 + tx];
            float xr[8] = {xA.x, xA.y, xA.z, xA.w, xB.x, xB.y, xB.z, xB.w};
            float res[8];
#pragma unroll
            for (int j = 0; j < 8; j++)
                res[j] = fmaxf(o[j] + bvv[j] + xr[j], 0.f);
            if (d != d_cur) {
                if (d_cur >= 0) {
                    float* p = agg + (long long)d_cur * DD + tx * 4;
                    asm volatile("red.global.add.v4.f32 [%0], {%1,%2,%3,%4};"
                                 :: "l"(p), "f"(sum[0]), "f"(sum[1]), "f"(sum[2]), "f"(sum[3]) : "memory");
                    asm volatile("red.global.add.v4.f32 [%0], {%1,%2,%3,%4};"
                                 :: "l"(p + 64), "f"(sum[4]), "f"(sum[5]), "f"(sum[6]), "f"(sum[7]) : "memory");
                }
                d_cur = d;
#pragma unroll
                for (int j = 0; j < 8; j++) sum[j] = res[j];
            } else {
#pragma unroll
                for (int j = 0; j < 8; j++) sum[j] += res[j];
            }
        }
    }
    if (d_cur >= 0) {
        float* p = agg + (long long)d_cur * DD + tx * 4;
        asm volatile("red.global.add.v4.f32 [%0], {%1,%2,%3,%4};"
                     :: "l"(p), "f"(sum[0]), "f"(sum[1]), "f"(sum[2]), "f"(sum[3]) : "memory");
        asm volatile("red.global.add.v4.f32 [%0], {%1,%2,%3,%4};"
                     :: "l"(p + 64), "f"(sum[4]), "f"(sum[5]), "f"(sum[6]), "f"(sum[7]) : "memory");
    }
}

// ===========================================================================
// bf16 split-mma node GEMM (M=64 tiles, pre-converted W):
// out[M,128] = act(A[M,128]@W + bias). 512 threads, 16 warps:
// w&3 -> m16 tile, w>>2 -> n32 quarter. 2 CTAs/SM.
// ===========================================================================
#define S_AH 0
#define S_AL 16384
#define S_WH 32768
#define S_WL 65536
#define S_BIAS 98304
#define S_TOTAL 98816

template <bool RELU>
__global__ void __launch_bounds__(512, 2)
tc_gemm(const float* __restrict__ A,
        const __nv_bfloat16* __restrict__ wtH, const __nv_bfloat16* __restrict__ wtL,
        const float* __restrict__ bias, float* __restrict__ out, int M) {
    extern __shared__ char smem[];
    const uint32_t sb = smem_u32(smem);
    const int tid = threadIdx.x;
    const int row0 = blockIdx.x * 64;

    // convert A (64 rows) -> swizzled bf16 hi/lo
    for (int idx = tid; idx < 64 * 32; idx += 512) {
        int m = idx >> 5;
        int k4 = idx & 31;
        float4 v = make_float4(0.f, 0.f, 0.f, 0.f);
        int gm = row0 + m;
        if (gm < M) v = ((const float4*)A)[(long long)gm * 32 + k4];
        uint32_t off = asw(m, k4 >> 1) + (k4 & 1) * 8;
        *(uint2*)(smem + S_AH + off) = make_uint2(packbf(v.x, v.y), packbf(v.z, v.w));
        *(uint2*)(smem + S_AL + off) = make_uint2(packbf(bflo(v.x), bflo(v.y)),
                                                  packbf(bflo(v.z), bflo(v.w)));
    }
    // copy pre-converted W tiles (swizzle at store)
    for (int idx = tid; idx < 128 * 16 * 2; idx += 512) {
        int half = idx >> 11;              // 0 = WH, 1 = WL
        int q = idx & 2047;
        int n = q >> 4;
        int c = q & 15;
        const __nv_bfloat16* src = half ? wtL : wtH;
        uint4 v = *(const uint4*)((const char*)(src + n * 128) + c * 16);
        *(uint4*)(smem + (half ? S_WL : S_WH) + asw(n, c)) = v;
    }
    if (tid < 128) ((float*)(smem + S_BIAS))[tid] = bias[tid];
    __syncthreads();

    const int w = tid >> 5;
    const int lane = tid & 31;
    const int m0 = (w & 3) * 16;
    const int nbase = (w >> 2) * 32;

    float c[4][4];
#pragma unroll
    for (int j = 0; j < 4; j++)
#pragma unroll
        for (int q = 0; q < 4; q++) c[j][q] = 0.f;

    const int ar = m0 + (lane & 15);
    const int ak = lane >> 4;
    const int br = (lane & 7) + ((lane >> 4) << 3);
    const int bk = (lane >> 3) & 1;

#pragma unroll
    for (int kc = 0; kc < 8; kc++) {
        uint32_t ah[4], al[4];
        uint32_t aaddr = asw(ar, kc * 2 + ak);
        LDSM_X4(ah, sb + S_AH + aaddr);
        LDSM_X4(al, sb + S_AL + aaddr);
#pragma unroll
        for (int jp = 0; jp < 2; jp++) {
            int nrow = nbase + jp * 16 + br;
            uint32_t baddr = asw(nrow, kc * 2 + bk);
            uint32_t bh[4], bl[4];
            LDSM_X4(bh, sb + S_WH + baddr);
            LDSM_X4(bl, sb + S_WL + baddr);
            mma16816(c[jp * 2],     ah, bh[0], bh[1]);
            mma16816(c[jp * 2],     ah, bl[0], bl[1]);
            mma16816(c[jp * 2],     al, bh[0], bh[1]);
            mma16816(c[jp * 2 + 1], ah, bh[2], bh[3]);
            mma16816(c[jp * 2 + 1], ah, bl[2], bl[3]);
            mma16816(c[jp * 2 + 1], al, bh[2], bh[3]);
        }
    }

    const int g = lane >> 2;
    const int tig = lane & 3;
    const int rlo = row0 + m0 + g;
    const int rhi = rlo + 8;
    const float* bs = (const float*)(smem + S_BIAS);
#pragma unroll
    for (int j = 0; j < 4; j++) {
        int n0 = nbase + j * 8 + tig * 2;
        float bb0 = bs[n0], bb1 = bs[n0 + 1];
        float v0 = c[j][0] + bb0, v1 = c[j][1] + bb1;
        float v2 = c[j][2] + bb0, v3 = c[j][3] + bb1;
        if (RELU) {
            v0 = fmaxf(v0, 0.f); v1 = fmaxf(v1, 0.f);
            v2 = fmaxf(v2, 0.f); v3 = fmaxf(v3, 0.f);
        }
        if (rlo < M) *(float2*)(out + (long long)rlo * DD + n0) = make_float2(v0, v1);
        if (rhi < M) *(float2*)(out + (long long)rhi * DD + n0) = make_float2(v2, v3);
    }
}

// ---------------------------------------------------------------------------
extern "C" void kernel_launch(void* const* d_in, const int* in_sizes, int n_in,
                              void* d_out, int out_size) {
    const float* x    = (const float*)d_in[0];
    const int*   ei   = (const int*)d_in[1];      // int32
    const float* ea   = (const float*)d_in[2];
    const float* w1_0 = (const float*)d_in[3];
    const float* b1_0 = (const float*)d_in[4];
    const float* w2_0 = (const float*)d_in[5];
    const float* b2_0 = (const float*)d_in[6];
    const float* we_0 = (const float*)d_in[7];
    const float* be_0 = (const float*)d_in[8];
    const float* w1_1 = (const float*)d_in[9];
    const float* b1_1 = (const float*)d_in[10];
    const float* w2_1 = (const float*)d_in[11];
    const float* b2_1 = (const float*)d_in[12];
    const float* we_1 = (const float*)d_in[13];
    const float* be_1 = (const float*)d_in[14];
    const float* fc1w = (const float*)d_in[15];
    const float* fc1b = (const float*)d_in[16];
    const float* fc2w = (const float*)d_in[17];
    const float* fc2b = (const float*)d_in[18];
    float* out = (float*)d_out;

    float *agg, *h, *t;
    cudaGetSymbolAddress((void**)&agg, g_agg);
    cudaGetSymbolAddress((void**)&h,   g_h);
    cudaGetSymbolAddress((void**)&t,   g_t);
    __nv_bfloat16 *wtH, *wtL, *weH, *weL;
    cudaGetSymbolAddress((void**)&wtH, g_wtH);
    cudaGetSymbolAddress((void**)&wtL, g_wtL);
    cudaGetSymbolAddress((void**)&weH, g_weH);
    cudaGetSymbolAddress((void**)&weL, g_weL);

    cudaFuncSetAttribute(tc_gemm<true>,  cudaFuncAttributeMaxDynamicSharedMemorySize, S_TOTAL);
    cudaFuncSetAttribute(tc_gemm<false>, cudaFuncAttributeMaxDynamicSharedMemorySize, S_TOTAL);
    cudaFuncSetAttribute(edge_fused_kernel, cudaFuncAttributeMaxDynamicSharedMemorySize, E_TOTAL);

    const int n4 = NN * (DD / 4);
    const int copyBlocks = (n4 + 255) / 256;
    const int prepBlocks = (26624 + NN + 255) / 256;  // 300
    const int edgeThreadBlocks = (NE + 255) / 256;
    const int fusedBlocks = (NE + 127) / 128;         // 4688
    const int tcBlocks = (NN + 63) / 64;              // 782

    // ---- prep: weights + zero cnt (1 launch) ----
    prep_kernel<<<prepBlocks, 256>>>(w1_0, w2_0, w1_1, w2_1, fc1w, fc2w, we_0, we_1);

    // ---- CSR build ----
    hist_kernel<<<edgeThreadBlocks, 256>>>(ei);
    scan_kernel<<<1, 1024>>>();
    scatter_conv_kernel<<<edgeThreadBlocks, 256>>>(ei, (const float4*)ea);

    // ---- Layer 0 ----
    copy4_kernel<<<copyBlocks, 256>>>((const float4*)x, (float4*)agg, n4);
    edge_fused_kernel<<<fusedBlocks, 256, E_TOTAL>>>(x, weH, weL, be_0, agg);
    tc_gemm<true><<<tcBlocks, 512, S_TOTAL>>>(agg, wtH + 0 * DD * DD, wtL + 0 * DD * DD, b1_0, t, NN);
    tc_gemm<true><<<tcBlocks, 512, S_TOTAL>>>(t,   wtH + 1 * DD * DD, wtL + 1 * DD * DD, b2_0, h, NN);

    // ---- Layer 1 ----
    copy4_kernel<<<copyBlocks, 256>>>((const float4*)h, (float4*)agg, n4);
    edge_fused_kernel<<<fusedBlocks, 256, E_TOTAL>>>(h, weH + DD * DE, weL + DD * DE, be_1, agg);
    tc_gemm<true><<<tcBlocks, 512, S_TOTAL>>>(agg, wtH + 2 * DD * DD, wtL + 2 * DD * DD, b1_1, t, NN);
    tc_gemm<true><<<tcBlocks, 512, S_TOTAL>>>(t,   wtH + 3 * DD * DD, wtL + 3 * DD * DD, b2_1, h, NN);

    // ---- Head ----
    tc_gemm<true><<<tcBlocks, 512, S_TOTAL>>>(h,  wtH + 4 * DD * DD, wtL + 4 * DD * DD, fc1b, t, NN);
    tc_gemm<false><<<tcBlocks, 512, S_TOTAL>>>(t, wtH + 5 * DD * DD, wtL + 5 * DD * DD, fc2b, out, NN);
}

// round 15
// speedup vs baseline: 1.0733x; 1.0733x over previous
#include <cuda_runtime.h>
#include <cuda_bf16.h>
#include <cstdint>

#define NN 50000
#define NE 600000
#define DD 128
#define DE 32

typedef unsigned long long u64;

// Scratch (device globals — no allocation allowed)
__device__ float g_agg[NN * DD];
__device__ float g_h[NN * DD];
__device__ float g_t[NN * DD];
__device__ int   g_rowptr[NN + 1];
__device__ int   g_woff[NN];
__device__ int   g_cnt[NN];
__device__ int   g_srcp[NE];
__device__ int   g_dstp[NE];
__device__ int   g_eidx[NE];
// pre-converted operands
__device__ __nv_bfloat16 g_eaH[(size_t)NE * DE];   // permuted edge_attr hi
__device__ __nv_bfloat16 g_eaL[(size_t)NE * DE];   // permuted edge_attr lo
__device__ __nv_bfloat16 g_wtH[6][DD * DD];        // node W transposed [n][k] hi
__device__ __nv_bfloat16 g_wtL[6][DD * DD];
__device__ __nv_bfloat16 g_weH[2][DD * DE];        // edge we transposed [n][k] hi
__device__ __nv_bfloat16 g_weL[2][DD * DE];

// ---- helpers ----
static __device__ __forceinline__ uint32_t smem_u32(const void* p) {
    uint32_t a;
    asm("{ .reg .u64 t; cvta.to.shared.u64 t, %1; cvt.u32.u64 %0, t; }" : "=r"(a) : "l"(p));
    return a;
}
static __device__ __forceinline__ uint32_t packbf(float a, float b) {
    __nv_bfloat16 ha = __float2bfloat16_rn(a), hb = __float2bfloat16_rn(b);
    uint16_t ua = *(uint16_t*)&ha, ub = *(uint16_t*)&hb;
    return (uint32_t)ua | ((uint32_t)ub << 16);
}
static __device__ __forceinline__ float bflo(float a) {
    __nv_bfloat16 h = __float2bfloat16_rn(a);
    return a - __bfloat162float(h);
}
// swizzled byte addr: 256B rows (128 bf16), chunk c in 0..15
static __device__ __forceinline__ uint32_t asw(int row, int c) {
    return (uint32_t)(row * 256 + ((c ^ (row & 7)) << 4));
}
// swizzled byte addr: 128B rows (64 bf16 = hi32|lo32), chunk c in 0..7
static __device__ __forceinline__ uint32_t asw128(int row, int c) {
    return (uint32_t)(row * 128 + ((c ^ (row & 7)) << 4));
}

#define LDSM_X4(r, a) \
    asm volatile("ldmatrix.sync.aligned.m8n8.x4.shared.b16 {%0,%1,%2,%3}, [%4];" \
        : "=r"((r)[0]), "=r"((r)[1]), "=r"((r)[2]), "=r"((r)[3]) : "r"(a))

__device__ __forceinline__ void mma16816(float* c, const uint32_t* a, uint32_t b0, uint32_t b1) {
    asm volatile("mma.sync.aligned.m16n8k16.row.col.f32.bf16.bf16.f32 "
        "{%0,%1,%2,%3}, {%4,%5,%6,%7}, {%8,%9}, {%0,%1,%2,%3};"
        : "+f"(c[0]), "+f"(c[1]), "+f"(c[2]), "+f"(c[3])
        : "r"(a[0]), "r"(a[1]), "r"(a[2]), "r"(a[3]), "r"(b0), "r"(b1));
}

// ===========================================================================
// prep kernel: all weight conversions + zero g_cnt, one launch.
// ===========================================================================
__global__ void prep_kernel(const float* __restrict__ w0, const float* __restrict__ w1,
                            const float* __restrict__ w2, const float* __restrict__ w3,
                            const float* __restrict__ w4, const float* __restrict__ w5,
                            const float* __restrict__ we0, const float* __restrict__ we1) {
    int gid = blockIdx.x * blockDim.x + threadIdx.x;
    if (gid < 24576) {
        int wi = gid >> 12;          // 0..5
        int idx = gid & 4095;
        const float* W = (wi == 0) ? w0 : (wi == 1) ? w1 : (wi == 2) ? w2
                       : (wi == 3) ? w3 : (wi == 4) ? w4 : w5;
        int n = idx & 127;
        int kq = idx >> 7;           // 0..31
        float v0 = W[(kq * 4 + 0) * 128 + n];
        float v1 = W[(kq * 4 + 1) * 128 + n];
        float v2 = W[(kq * 4 + 2) * 128 + n];
        float v3 = W[(kq * 4 + 3) * 128 + n];
        *(uint2*)(&g_wtH[wi][n * 128 + kq * 4]) = make_uint2(packbf(v0, v1), packbf(v2, v3));
        *(uint2*)(&g_wtL[wi][n * 128 + kq * 4]) =
            make_uint2(packbf(bflo(v0), bflo(v1)), packbf(bflo(v2), bflo(v3)));
    } else if (gid < 26624) {
        int q = gid - 24576;
        int wi = q >> 10;            // 0..1
        int idx = q & 1023;
        const float* W = wi ? we1 : we0;
        int n = idx & 127;
        int kq = idx >> 7;           // 0..7
        float v0 = W[(kq * 4 + 0) * 128 + n];
        float v1 = W[(kq * 4 + 1) * 128 + n];
        float v2 = W[(kq * 4 + 2) * 128 + n];
        float v3 = W[(kq * 4 + 3) * 128 + n];
        *(uint2*)(&g_weH[wi][n * 32 + kq * 4]) = make_uint2(packbf(v0, v1), packbf(v2, v3));
        *(uint2*)(&g_weL[wi][n * 32 + kq * 4]) =
            make_uint2(packbf(bflo(v0), bflo(v1)), packbf(bflo(v2), bflo(v3)));
    } else {
        int n = gid - 26624;
        if (n < NN) g_cnt[n] = 0;
    }
}

// ===========================================================================
// CSR build
// ===========================================================================
__global__ void hist_kernel(const int* __restrict__ ei) {
    int i = blockIdx.x * blockDim.x + threadIdx.x;
    if (i < NE) atomicAdd(&g_cnt[ei[NE + i]], 1);
}

__global__ void scan_kernel() {
    __shared__ int s[1024];
    const int tid = threadIdx.x;
    const int CH = (NN + 1023) / 1024;
    const int base = tid * CH;
    const int end = min(base + CH, NN);
    int tot = 0;
    for (int i = base; i < end; i++) tot += g_cnt[i];
    s[tid] = tot;
    __syncthreads();
#pragma unroll
    for (int off = 1; off < 1024; off <<= 1) {
        int t = (tid >= off) ? s[tid - off] : 0;
        __syncthreads();
        s[tid] += t;
        __syncthreads();
    }
    int run = s[tid] - tot;
    for (int i = base; i < end; i++) {
        int v = g_cnt[i];
        g_rowptr[i] = run;
        g_woff[i] = run;
        run += v;
    }
    if (end == NN) g_rowptr[NN] = run;
}

__global__ void scatter_kernel(const int* __restrict__ ei) {
    int i = blockIdx.x * blockDim.x + threadIdx.x;
    if (i < NE) {
        int d = ei[NE + i];
        int p = atomicAdd(&g_woff[d], 1);
        g_srcp[p] = ei[i];
        g_dstp[p] = d;
        g_eidx[p] = i;
    }
}

// permute + convert edge_attr: sequential writes, gathered reads.
__global__ void conv_ea_kernel(const float4* __restrict__ ea4) {
    long long t = (long long)blockIdx.x * blockDim.x + threadIdx.x;
    if (t < (long long)NE * 4) {
        long long i = t >> 2;
        int c = (int)(t & 3);
        int e = g_eidx[i];
        float4 v0 = ea4[(long long)e * 8 + c * 2];
        float4 v1 = ea4[(long long)e * 8 + c * 2 + 1];
        uint4 hi = make_uint4(packbf(v0.x, v0.y), packbf(v0.z, v0.w),
                              packbf(v1.x, v1.y), packbf(v1.z, v1.w));
        uint4 lo = make_uint4(packbf(bflo(v0.x), bflo(v0.y)), packbf(bflo(v0.z), bflo(v0.w)),
                              packbf(bflo(v1.x), bflo(v1.y)), packbf(bflo(v1.z), bflo(v1.w)));
        *(uint4*)((char*)g_eaH + i * 64 + c * 16) = hi;
        *(uint4*)((char*)g_eaL + i * 64 + c * 16) = lo;
    }
}

__global__ void copy4_kernel(const float4* __restrict__ s, float4* __restrict__ d, int n4) {
    int i = blockIdx.x * blockDim.x + threadIdx.x;
    if (i < n4) d[i] = s[i];
}

// ===========================================================================
// Edge kernel (mma): emb = ea@we via bf16-split mma -> Msg smem;
// epilogue = segmented reduction (relu(emb+be+x[src]) summed per dst run).
// ===========================================================================
#define E_EA  0
#define E_WE  16384
#define E_MSG 32768
#define E_TOTAL (32768 + 128 * 528)      // 100352
#define MSG_STRIDE 132                   // floats; 528B rows

__global__ void __launch_bounds__(256, 2)
edge_fused_kernel(const float* __restrict__ xin,
                  const __nv_bfloat16* __restrict__ weH,
                  const __nv_bfloat16* __restrict__ weL,
                  const float* __restrict__ be,
                  float* __restrict__ agg) {
    extern __shared__ char smem[];
    const uint32_t sb = smem_u32(smem);
    float* MsgS = (float*)(smem + E_MSG);
    const int tid = threadIdx.x;
    const long long i0 = (long long)blockIdx.x * 128;

    // load Ea tile (hi|lo 128B rows, swizzled) + We tile
#pragma unroll
    for (int l = 0; l < 4; l++) {
        int idx = tid + l * 256;          // 0..1023 : Ea
        int r = idx >> 3;
        int c = idx & 7;
        long long gi = i0 + r;
        uint4 v = make_uint4(0, 0, 0, 0);
        if (gi < NE) {
            const char* src = (c < 4) ? ((const char*)g_eaH + gi * 64 + c * 16)
                                      : ((const char*)g_eaL + gi * 64 + (c - 4) * 16);
            v = *(const uint4*)src;
        }
        *(uint4*)(smem + E_EA + asw128(r, c)) = v;
        // We
        const char* ws = (c < 4) ? ((const char*)weH + r * 64 + c * 16)
                                 : ((const char*)weL + r * 64 + (c - 4) * 16);
        *(uint4*)(smem + E_WE + asw128(r, c)) = *(const uint4*)ws;
    }
    __syncthreads();

    // ---- mma: 8 warps, warp w -> rows [w*16, w*16+16), cols 0..127 ----
    {
        const int w = tid >> 5;
        const int lane = tid & 31;
        const int m0 = w * 16;
        const int ar = m0 + (lane & 15);
        const int ak = lane >> 4;
        const int br = (lane & 7) + ((lane >> 4) << 3);
        const int bk = (lane >> 3) & 1;

        float c[16][4];
#pragma unroll
        for (int j = 0; j < 16; j++)
#pragma unroll
            for (int q = 0; q < 4; q++) c[j][q] = 0.f;

#pragma unroll
        for (int s = 0; s < 2; s++) {
            uint32_t ah[4], al[4];
            LDSM_X4(ah, sb + E_EA + asw128(ar, 2 * s + ak));
            LDSM_X4(al, sb + E_EA + asw128(ar, 4 + 2 * s + ak));
#pragma unroll
            for (int jp = 0; jp < 8; jp++) {
                int nrow = jp * 16 + br;
                uint32_t bh[4], bl[4];
                LDSM_X4(bh, sb + E_WE + asw128(nrow, 2 * s + bk));
                LDSM_X4(bl, sb + E_WE + asw128(nrow, 4 + 2 * s + bk));
                mma16816(c[jp * 2],     ah, bh[0], bh[1]);
                mma16816(c[jp * 2],     ah, bl[0], bl[1]);
                mma16816(c[jp * 2],     al, bh[0], bh[1]);
                mma16816(c[jp * 2 + 1], ah, bh[2], bh[3]);
                mma16816(c[jp * 2 + 1], ah, bl[2], bl[3]);
                mma16816(c[jp * 2 + 1], al, bh[2], bh[3]);
            }
        }
        // park emb in Msg smem (row-major, padded rows)
        const int g = lane >> 2;
        const int tig = lane & 3;
#pragma unroll
        for (int j = 0; j < 16; j++) {
            int col = j * 8 + tig * 2;
            *(float2*)(MsgS + (m0 + g) * MSG_STRIDE + col)     = make_float2(c[j][0], c[j][1]);
            *(float2*)(MsgS + (m0 + g + 8) * MSG_STRIDE + col) = make_float2(c[j][2], c[j][3]);
        }
    }
    __syncthreads();

    // ---- epilogue: segmented reduction over dst runs (cols tx*4 and 64+tx*4) ----
    const int tx = tid & 15;
    const int ty = tid >> 4;
    float4 bvA = *(const float4*)(be + tx * 4);
    float4 bvB = *(const float4*)(be + 64 + tx * 4);
    float bvv[8] = {bvA.x, bvA.y, bvA.z, bvA.w, bvB.x, bvB.y, bvB.z, bvB.w};

    int d_cur = -1;
    float sum[8];
#pragma unroll
    for (int rr = 0; rr < 8; rr++) {
        long long gi = i0 + ty * 8 + rr;
        if (gi < NE) {
            int d = g_dstp[gi];
            int src = g_srcp[gi];
            int row = ty * 8 + rr;
            float4 oA = *(const float4*)(MsgS + row * MSG_STRIDE + tx * 4);
            float4 oB = *(const float4*)(MsgS + row * MSG_STRIDE + 64 + tx * 4);
            float o[8] = {oA.x, oA.y, oA.z, oA.w, oB.x, oB.y, oB.z, oB.w};
            float4 xA = ((const float4*)xin)[(long long)src * 32 + tx];
            float4 xB = ((const float4*)xin)[(long long)src * 32 + 16 + tx];
            float xr[8] = {xA.x, xA.y, xA.z, xA.w, xB.x, xB.y, xB.z, xB.w};
            float res[8];
#pragma unroll
            for (int j = 0; j < 8; j++)
                res[j] = fmaxf(o[j] + bvv[j] + xr[j], 0.f);
            if (d != d_cur) {
                if (d_cur >= 0) {
                    float* p = agg + (long long)d_cur * DD + tx * 4;
                    asm volatile("red.global.add.v4.f32 [%0], {%1,%2,%3,%4};"
                                 :: "l"(p), "f"(sum[0]), "f"(sum[1]), "f"(sum[2]), "f"(sum[3]) : "memory");
                    asm volatile("red.global.add.v4.f32 [%0], {%1,%2,%3,%4};"
                                 :: "l"(p + 64), "f"(sum[4]), "f"(sum[5]), "f"(sum[6]), "f"(sum[7]) : "memory");
                }
                d_cur = d;
#pragma unroll
                for (int j = 0; j < 8; j++) sum[j] = res[j];
            } else {
#pragma unroll
                for (int j = 0; j < 8; j++) sum[j] += res[j];
            }
        }
    }
    if (d_cur >= 0) {
        float* p = agg + (long long)d_cur * DD + tx * 4;
        asm volatile("red.global.add.v4.f32 [%0], {%1,%2,%3,%4};"
                     :: "l"(p), "f"(sum[0]), "f"(sum[1]), "f"(sum[2]), "f"(sum[3]) : "memory");
        asm volatile("red.global.add.v4.f32 [%0], {%1,%2,%3,%4};"
                     :: "l"(p + 64), "f"(sum[4]), "f"(sum[5]), "f"(sum[6]), "f"(sum[7]) : "memory");
    }
}

// ===========================================================================
// bf16 split-mma node GEMM (M=64 tiles, pre-converted W)
// ===========================================================================
#define S_AH 0
#define S_AL 16384
#define S_WH 32768
#define S_WL 65536
#define S_BIAS 98304
#define S_TOTAL 98816

template <bool RELU>
__global__ void __launch_bounds__(512, 2)
tc_gemm(const float* __restrict__ A,
        const __nv_bfloat16* __restrict__ wtH, const __nv_bfloat16* __restrict__ wtL,
        const float* __restrict__ bias, float* __restrict__ out, int M) {
    extern __shared__ char smem[];
    const uint32_t sb = smem_u32(smem);
    const int tid = threadIdx.x;
    const int row0 = blockIdx.x * 64;

    // convert A (64 rows) -> swizzled bf16 hi/lo
    for (int idx = tid; idx < 64 * 32; idx += 512) {
        int m = idx >> 5;
        int k4 = idx & 31;
        float4 v = make_float4(0.f, 0.f, 0.f, 0.f);
        int gm = row0 + m;
        if (gm < M) v = ((const float4*)A)[(long long)gm * 32 + k4];
        uint32_t off = asw(m, k4 >> 1) + (k4 & 1) * 8;
        *(uint2*)(smem + S_AH + off) = make_uint2(packbf(v.x, v.y), packbf(v.z, v.w));
        *(uint2*)(smem + S_AL + off) = make_uint2(packbf(bflo(v.x), bflo(v.y)),
                                                  packbf(bflo(v.z), bflo(v.w)));
    }
    // copy pre-converted W tiles (swizzle at store)
    for (int idx = tid; idx < 128 * 16 * 2; idx += 512) {
        int half = idx >> 11;              // 0 = WH, 1 = WL
        int q = idx & 2047;
        int n = q >> 4;
        int c = q & 15;
        const __nv_bfloat16* src = half ? wtL : wtH;
        uint4 v = *(const uint4*)((const char*)(src + n * 128) + c * 16);
        *(uint4*)(smem + (half ? S_WL : S_WH) + asw(n, c)) = v;
    }
    if (tid < 128) ((float*)(smem + S_BIAS))[tid] = bias[tid];
    __syncthreads();

    const int w = tid >> 5;
    const int lane = tid & 31;
    const int m0 = (w & 3) * 16;
    const int nbase = (w >> 2) * 32;

    float c[4][4];
#pragma unroll
    for (int j = 0; j < 4; j++)
#pragma unroll
        for (int q = 0; q < 4; q++) c[j][q] = 0.f;

    const int ar = m0 + (lane & 15);
    const int ak = lane >> 4;
    const int br = (lane & 7) + ((lane >> 4) << 3);
    const int bk = (lane >> 3) & 1;

#pragma unroll
    for (int kc = 0; kc < 8; kc++) {
        uint32_t ah[4], al[4];
        uint32_t aaddr = asw(ar, kc * 2 + ak);
        LDSM_X4(ah, sb + S_AH + aaddr);
        LDSM_X4(al, sb + S_AL + aaddr);
#pragma unroll
        for (int jp = 0; jp < 2; jp++) {
            int nrow = nbase + jp * 16 + br;
            uint32_t baddr = asw(nrow, kc * 2 + bk);
            uint32_t bh[4], bl[4];
            LDSM_X4(bh, sb + S_WH + baddr);
            LDSM_X4(bl, sb + S_WL + baddr);
            mma16816(c[jp * 2],     ah, bh[0], bh[1]);
            mma16816(c[jp * 2],     ah, bl[0], bl[1]);
            mma16816(c[jp * 2],     al, bh[0], bh[1]);
            mma16816(c[jp * 2 + 1], ah, bh[2], bh[3]);
            mma16816(c[jp * 2 + 1], ah, bl[2], bl[3]);
            mma16816(c[jp * 2 + 1], al, bh[2], bh[3]);
        }
    }

    const int g = lane >> 2;
    const int tig = lane & 3;
    const int rlo = row0 + m0 + g;
    const int rhi = rlo + 8;
    const float* bs = (const float*)(smem + S_BIAS);
#pragma unroll
    for (int j = 0; j < 4; j++) {
        int n0 = nbase + j * 8 + tig * 2;
        float bb0 = bs[n0], bb1 = bs[n0 + 1];
        float v0 = c[j][0] + bb0, v1 = c[j][1] + bb1;
        float v2 = c[j][2] + bb0, v3 = c[j][3] + bb1;
        if (RELU) {
            v0 = fmaxf(v0, 0.f); v1 = fmaxf(v1, 0.f);
            v2 = fmaxf(v2, 0.f); v3 = fmaxf(v3, 0.f);
        }
        if (rlo < M) *(float2*)(out + (long long)rlo * DD + n0) = make_float2(v0, v1);
        if (rhi < M) *(float2*)(out + (long long)rhi * DD + n0) = make_float2(v2, v3);
    }
}

// ---------------------------------------------------------------------------
extern "C" void kernel_launch(void* const* d_in, const int* in_sizes, int n_in,
                              void* d_out, int out_size) {
    const float* x    = (const float*)d_in[0];
    const int*   ei   = (const int*)d_in[1];      // int32
    const float* ea   = (const float*)d_in[2];
    const float* w1_0 = (const float*)d_in[3];
    const float* b1_0 = (const float*)d_in[4];
    const float* w2_0 = (const float*)d_in[5];
    const float* b2_0 = (const float*)d_in[6];
    const float* we_0 = (const float*)d_in[7];
    const float* be_0 = (const float*)d_in[8];
    const float* w1_1 = (const float*)d_in[9];
    const float* b1_1 = (const float*)d_in[10];
    const float* w2_1 = (const float*)d_in[11];
    const float* b2_1 = (const float*)d_in[12];
    const float* we_1 = (const float*)d_in[13];
    const float* be_1 = (const float*)d_in[14];
    const float* fc1w = (const float*)d_in[15];
    const float* fc1b = (const float*)d_in[16];
    const float* fc2w = (const float*)d_in[17];
    const float* fc2b = (const float*)d_in[18];
    float* out = (float*)d_out;

    float *agg, *h, *t;
    cudaGetSymbolAddress((void**)&agg, g_agg);
    cudaGetSymbolAddress((void**)&h,   g_h);
    cudaGetSymbolAddress((void**)&t,   g_t);
    __nv_bfloat16 *wtH, *wtL, *weH, *weL;
    cudaGetSymbolAddress((void**)&wtH, g_wtH);
    cudaGetSymbolAddress((void**)&wtL, g_wtL);
    cudaGetSymbolAddress((void**)&weH, g_weH);
    cudaGetSymbolAddress((void**)&weL, g_weL);

    cudaFuncSetAttribute(tc_gemm<true>,  cudaFuncAttributeMaxDynamicSharedMemorySize, S_TOTAL);
    cudaFuncSetAttribute(tc_gemm<false>, cudaFuncAttributeMaxDynamicSharedMemorySize, S_TOTAL);
    cudaFuncSetAttribute(edge_fused_kernel, cudaFuncAttributeMaxDynamicSharedMemorySize, E_TOTAL);

    const int n4 = NN * (DD / 4);
    const int copyBlocks = (n4 + 255) / 256;
    const int prepBlocks = (26624 + NN + 255) / 256;  // 300
    const int edgeThreadBlocks = (NE + 255) / 256;
    const int convEaBlocks = (int)(((long long)NE * 4 + 255) / 256);
    const int fusedBlocks = (NE + 127) / 128;         // 4688
    const int tcBlocks = (NN + 63) / 64;              // 782

    // ---- prep: weights + zero cnt (1 launch) ----
    prep_kernel<<<prepBlocks, 256>>>(w1_0, w2_0, w1_1, w2_1, fc1w, fc2w, we_0, we_1);

    // ---- CSR build ----
    hist_kernel<<<edgeThreadBlocks, 256>>>(ei);
    scan_kernel<<<1, 1024>>>();
    scatter_kernel<<<edgeThreadBlocks, 256>>>(ei);
    conv_ea_kernel<<<convEaBlocks, 256>>>((const float4*)ea);

    // ---- Layer 0 ----
    copy4_kernel<<<copyBlocks, 256>>>((const float4*)x, (float4*)agg, n4);
    edge_fused_kernel<<<fusedBlocks, 256, E_TOTAL>>>(x, weH, weL, be_0, agg);
    tc_gemm<true><<<tcBlocks, 512, S_TOTAL>>>(agg, wtH + 0 * DD * DD, wtL + 0 * DD * DD, b1_0, t, NN);
    tc_gemm<true><<<tcBlocks, 512, S_TOTAL>>>(t,   wtH + 1 * DD * DD, wtL + 1 * DD * DD, b2_0, h, NN);

    // ---- Layer 1 ----
    copy4_kernel<<<copyBlocks, 256>>>((const float4*)h, (float4*)agg, n4);
    edge_fused_kernel<<<fusedBlocks, 256, E_TOTAL>>>(h, weH + DD * DE, weL + DD * DE, be_1, agg);
    tc_gemm<true><<<tcBlocks, 512, S_TOTAL>>>(agg, wtH + 2 * DD * DD, wtL + 2 * DD * DD, b1_1, t, NN);
    tc_gemm<true><<<tcBlocks, 512, S_TOTAL>>>(t,   wtH + 3 * DD * DD, wtL + 3 * DD * DD, b2_1, h, NN);

    // ---- Head ----
    tc_gemm<true><<<tcBlocks, 512, S_TOTAL>>>(h,  wtH + 4 * DD * DD, wtL + 4 * DD * DD, fc1b, t, NN);
    tc_gemm<false><<<tcBlocks, 512, S_TOTAL>>>(t, wtH + 5 * DD * DD, wtL + 5 * DD * DD, fc2b, out, NN);
}

// round 17
// speedup vs baseline: 1.1224x; 1.0458x over previous
#include <cuda_runtime.h>
#include <cuda_bf16.h>
#include <cstdint>

#define NN 50000
#define NE 600000
#define DD 128
#define DE 32

typedef unsigned long long u64;

// Scratch (device globals — no allocation allowed)
__device__ float g_agg[NN * DD];
__device__ float g_h[NN * DD];
__device__ int   g_rowptr[NN + 1];
__device__ int   g_woff[NN];
__device__ int   g_cnt[NN];
__device__ int   g_srcp[NE];
__device__ int   g_dstp[NE];
__device__ int   g_eidx[NE];
// pre-converted operands
__device__ __nv_bfloat16 g_eaH[(size_t)NE * DE];   // permuted edge_attr hi
__device__ __nv_bfloat16 g_eaL[(size_t)NE * DE];   // permuted edge_attr lo
__device__ __nv_bfloat16 g_wtH[6][DD * DD];        // node W transposed [n][k] hi
__device__ __nv_bfloat16 g_wtL[6][DD * DD];
__device__ __nv_bfloat16 g_weH[2][DD * DE];        // edge we transposed [n][k] hi
__device__ __nv_bfloat16 g_weL[2][DD * DE];

// ---- helpers ----
static __device__ __forceinline__ uint32_t smem_u32(const void* p) {
    uint32_t a;
    asm("{ .reg .u64 t; cvta.to.shared.u64 t, %1; cvt.u32.u64 %0, t; }" : "=r"(a) : "l"(p));
    return a;
}
static __device__ __forceinline__ uint32_t packbf(float a, float b) {
    __nv_bfloat16 ha = __float2bfloat16_rn(a), hb = __float2bfloat16_rn(b);
    uint16_t ua = *(uint16_t*)&ha, ub = *(uint16_t*)&hb;
    return (uint32_t)ua | ((uint32_t)ub << 16);
}
static __device__ __forceinline__ float bflo(float a) {
    __nv_bfloat16 h = __float2bfloat16_rn(a);
    return a - __bfloat162float(h);
}
// swizzled byte addr: 256B rows (128 bf16), chunk c in 0..15
static __device__ __forceinline__ uint32_t asw(int row, int c) {
    return (uint32_t)(row * 256 + ((c ^ (row & 7)) << 4));
}
// swizzled byte addr: 128B rows (64 bf16 = hi32|lo32), chunk c in 0..7
static __device__ __forceinline__ uint32_t asw128(int row, int c) {
    return (uint32_t)(row * 128 + ((c ^ (row & 7)) << 4));
}

#define LDSM_X4(r, a) \
    asm volatile("ldmatrix.sync.aligned.m8n8.x4.shared.b16 {%0,%1,%2,%3}, [%4];" \
        : "=r"((r)[0]), "=r"((r)[1]), "=r"((r)[2]), "=r"((r)[3]) : "r"(a))

__device__ __forceinline__ void mma16816(float* c, const uint32_t* a, uint32_t b0, uint32_t b1) {
    asm volatile("mma.sync.aligned.m16n8k16.row.col.f32.bf16.bf16.f32 "
        "{%0,%1,%2,%3}, {%4,%5,%6,%7}, {%8,%9}, {%0,%1,%2,%3};"
        : "+f"(c[0]), "+f"(c[1]), "+f"(c[2]), "+f"(c[3])
        : "r"(a[0]), "r"(a[1]), "r"(a[2]), "r"(a[3]), "r"(b0), "r"(b1));
}

// ===========================================================================
// prep kernel: all weight conversions + zero g_cnt, one launch.
// ===========================================================================
__global__ void prep_kernel(const float* __restrict__ w0, const float* __restrict__ w1,
                            const float* __restrict__ w2, const float* __restrict__ w3,
                            const float* __restrict__ w4, const float* __restrict__ w5,
                            const float* __restrict__ we0, const float* __restrict__ we1) {
    int gid = blockIdx.x * blockDim.x + threadIdx.x;
    if (gid < 24576) {
        int wi = gid >> 12;          // 0..5
        int idx = gid & 4095;
        const float* W = (wi == 0) ? w0 : (wi == 1) ? w1 : (wi == 2) ? w2
                       : (wi == 3) ? w3 : (wi == 4) ? w4 : w5;
        int n = idx & 127;
        int kq = idx >> 7;           // 0..31
        float v0 = W[(kq * 4 + 0) * 128 + n];
        float v1 = W[(kq * 4 + 1) * 128 + n];
        float v2 = W[(kq * 4 + 2) * 128 + n];
        float v3 = W[(kq * 4 + 3) * 128 + n];
        *(uint2*)(&g_wtH[wi][n * 128 + kq * 4]) = make_uint2(packbf(v0, v1), packbf(v2, v3));
        *(uint2*)(&g_wtL[wi][n * 128 + kq * 4]) =
            make_uint2(packbf(bflo(v0), bflo(v1)), packbf(bflo(v2), bflo(v3)));
    } else if (gid < 26624) {
        int q = gid - 24576;
        int wi = q >> 10;            // 0..1
        int idx = q & 1023;
        const float* W = wi ? we1 : we0;
        int n = idx & 127;
        int kq = idx >> 7;           // 0..7
        float v0 = W[(kq * 4 + 0) * 128 + n];
        float v1 = W[(kq * 4 + 1) * 128 + n];
        float v2 = W[(kq * 4 + 2) * 128 + n];
        float v3 = W[(kq * 4 + 3) * 128 + n];
        *(uint2*)(&g_weH[wi][n * 32 + kq * 4]) = make_uint2(packbf(v0, v1), packbf(v2, v3));
        *(uint2*)(&g_weL[wi][n * 32 + kq * 4]) =
            make_uint2(packbf(bflo(v0), bflo(v1)), packbf(bflo(v2), bflo(v3)));
    } else {
        int n = gid - 26624;
        if (n < NN) g_cnt[n] = 0;
    }
}

// ===========================================================================
// CSR build
// ===========================================================================
__global__ void hist_kernel(const int* __restrict__ ei) {
    int i = blockIdx.x * blockDim.x + threadIdx.x;
    if (i < NE) atomicAdd(&g_cnt[ei[NE + i]], 1);
}

__global__ void scan_kernel() {
    __shared__ int s[1024];
    const int tid = threadIdx.x;
    const int CH = (NN + 1023) / 1024;
    const int base = tid * CH;
    const int end = min(base + CH, NN);
    int tot = 0;
    for (int i = base; i < end; i++) tot += g_cnt[i];
    s[tid] = tot;
    __syncthreads();
#pragma unroll
    for (int off = 1; off < 1024; off <<= 1) {
        int t = (tid >= off) ? s[tid - off] : 0;
        __syncthreads();
        s[tid] += t;
        __syncthreads();
    }
    int run = s[tid] - tot;
    for (int i = base; i < end; i++) {
        int v = g_cnt[i];
        g_rowptr[i] = run;
        g_woff[i] = run;
        run += v;
    }
    if (end == NN) g_rowptr[NN] = run;
}

__global__ void scatter_kernel(const int* __restrict__ ei) {
    int i = blockIdx.x * blockDim.x + threadIdx.x;
    if (i < NE) {
        int d = ei[NE + i];
        int p = atomicAdd(&g_woff[d], 1);
        g_srcp[p] = ei[i];
        g_dstp[p] = d;
        g_eidx[p] = i;
    }
}

// permute + convert edge_attr: sequential writes, gathered reads.
__global__ void conv_ea_kernel(const float4* __restrict__ ea4) {
    long long t = (long long)blockIdx.x * blockDim.x + threadIdx.x;
    if (t < (long long)NE * 4) {
        long long i = t >> 2;
        int c = (int)(t & 3);
        int e = g_eidx[i];
        float4 v0 = ea4[(long long)e * 8 + c * 2];
        float4 v1 = ea4[(long long)e * 8 + c * 2 + 1];
        uint4 hi = make_uint4(packbf(v0.x, v0.y), packbf(v0.z, v0.w),
                              packbf(v1.x, v1.y), packbf(v1.z, v1.w));
        uint4 lo = make_uint4(packbf(bflo(v0.x), bflo(v0.y)), packbf(bflo(v0.z), bflo(v0.w)),
                              packbf(bflo(v1.x), bflo(v1.y)), packbf(bflo(v1.z), bflo(v1.w)));
        *(uint4*)((char*)g_eaH + i * 64 + c * 16) = hi;
        *(uint4*)((char*)g_eaL + i * 64 + c * 16) = lo;
    }
}

__global__ void copy4_kernel(const float4* __restrict__ s, float4* __restrict__ d, int n4) {
    int i = blockIdx.x * blockDim.x + threadIdx.x;
    if (i < n4) d[i] = s[i];
}

// ===========================================================================
// Edge kernel (mma): emb = ea@we via bf16-split mma -> Msg smem;
// epilogue = segmented reduction (relu(emb+be+x[src]) summed per dst run).
// ===========================================================================
#define E_EA  0
#define E_WE  16384
#define E_MSG 32768
#define E_TOTAL (32768 + 128 * 528)      // 100352
#define MSG_STRIDE 132                   // floats; 528B rows

__global__ void __launch_bounds__(256, 2)
edge_fused_kernel(const float* __restrict__ xin,
                  const __nv_bfloat16* __restrict__ weH,
                  const __nv_bfloat16* __restrict__ weL,
                  const float* __restrict__ be,
                  float* __restrict__ agg) {
    extern __shared__ char smem[];
    const uint32_t sb = smem_u32(smem);
    float* MsgS = (float*)(smem + E_MSG);
    const int tid = threadIdx.x;
    const long long i0 = (long long)blockIdx.x * 128;

    // load Ea tile (hi|lo 128B rows, swizzled) + We tile
#pragma unroll
    for (int l = 0; l < 4; l++) {
        int idx = tid + l * 256;          // 0..1023 : Ea
        int r = idx >> 3;
        int c = idx & 7;
        long long gi = i0 + r;
        uint4 v = make_uint4(0, 0, 0, 0);
        if (gi < NE) {
            const char* src = (c < 4) ? ((const char*)g_eaH + gi * 64 + c * 16)
                                      : ((const char*)g_eaL + gi * 64 + (c - 4) * 16);
            v = *(const uint4*)src;
        }
        *(uint4*)(smem + E_EA + asw128(r, c)) = v;
        // We
        const char* ws = (c < 4) ? ((const char*)weH + r * 64 + c * 16)
                                 : ((const char*)weL + r * 64 + (c - 4) * 16);
        *(uint4*)(smem + E_WE + asw128(r, c)) = *(const uint4*)ws;
    }
    __syncthreads();

    // ---- mma: 8 warps, warp w -> rows [w*16, w*16+16), cols 0..127 ----
    {
        const int w = tid >> 5;
        const int lane = tid & 31;
        const int m0 = w * 16;
        const int ar = m0 + (lane & 15);
        const int ak = lane >> 4;
        const int br = (lane & 7) + ((lane >> 4) << 3);
        const int bk = (lane >> 3) & 1;

        float c[16][4];
#pragma unroll
        for (int j = 0; j < 16; j++)
#pragma unroll
            for (int q = 0; q < 4; q++) c[j][q] = 0.f;

#pragma unroll
        for (int s = 0; s < 2; s++) {
            uint32_t ah[4], al[4];
            LDSM_X4(ah, sb + E_EA + asw128(ar, 2 * s + ak));
            LDSM_X4(al, sb + E_EA + asw128(ar, 4 + 2 * s + ak));
#pragma unroll
            for (int jp = 0; jp < 8; jp++) {
                int nrow = jp * 16 + br;
                uint32_t bh[4], bl[4];
                LDSM_X4(bh, sb + E_WE + asw128(nrow, 2 * s + bk));
                LDSM_X4(bl, sb + E_WE + asw128(nrow, 4 + 2 * s + bk));
                mma16816(c[jp * 2],     ah, bh[0], bh[1]);
                mma16816(c[jp * 2],     ah, bl[0], bl[1]);
                mma16816(c[jp * 2],     al, bh[0], bh[1]);
                mma16816(c[jp * 2 + 1], ah, bh[2], bh[3]);
                mma16816(c[jp * 2 + 1], ah, bl[2], bl[3]);
                mma16816(c[jp * 2 + 1], al, bh[2], bh[3]);
            }
        }
        // park emb in Msg smem (row-major, padded rows)
        const int g = lane >> 2;
        const int tig = lane & 3;
#pragma unroll
        for (int j = 0; j < 16; j++) {
            int col = j * 8 + tig * 2;
            *(float2*)(MsgS + (m0 + g) * MSG_STRIDE + col)     = make_float2(c[j][0], c[j][1]);
            *(float2*)(MsgS + (m0 + g + 8) * MSG_STRIDE + col) = make_float2(c[j][2], c[j][3]);
        }
    }
    __syncthreads();

    // ---- epilogue: segmented reduction over dst runs (cols tx*4 and 64+tx*4) ----
    const int tx = tid & 15;
    const int ty = tid >> 4;
    float4 bvA = *(const float4*)(be + tx * 4);
    float4 bvB = *(const float4*)(be + 64 + tx * 4);
    float bvv[8] = {bvA.x, bvA.y, bvA.z, bvA.w, bvB.x, bvB.y, bvB.z, bvB.w};

    int d_cur = -1;
    float sum[8];
#pragma unroll
    for (int rr = 0; rr < 8; rr++) {
        long long gi = i0 + ty * 8 + rr;
        if (gi < NE) {
            int d = g_dstp[gi];
            int src = g_srcp[gi];
            int row = ty * 8 + rr;
            float4 oA = *(const float4*)(MsgS + row * MSG_STRIDE + tx * 4);
            float4 oB = *(const float4*)(MsgS + row * MSG_STRIDE + 64 + tx * 4);
            float o[8] = {oA.x, oA.y, oA.z, oA.w, oB.x, oB.y, oB.z, oB.w};
            float4 xA = ((const float4*)xin)[(long long)src * 32 + tx];
            float4 xB = ((const float4*)xin)[(long long)src * 32 + 16 + tx];
            float xr[8] = {xA.x, xA.y, xA.z, xA.w, xB.x, xB.y, xB.z, xB.w};
            float res[8];
#pragma unroll
            for (int j = 0; j < 8; j++)
                res[j] = fmaxf(o[j] + bvv[j] + xr[j], 0.f);
            if (d != d_cur) {
                if (d_cur >= 0) {
                    float* p = agg + (long long)d_cur * DD + tx * 4;
                    asm volatile("red.global.add.v4.f32 [%0], {%1,%2,%3,%4};"
                                 :: "l"(p), "f"(sum[0]), "f"(sum[1]), "f"(sum[2]), "f"(sum[3]) : "memory");
                    asm volatile("red.global.add.v4.f32 [%0], {%1,%2,%3,%4};"
                                 :: "l"(p + 64), "f"(sum[4]), "f"(sum[5]), "f"(sum[6]), "f"(sum[7]) : "memory");
                }
                d_cur = d;
#pragma unroll
                for (int j = 0; j < 8; j++) sum[j] = res[j];
            } else {
#pragma unroll
                for (int j = 0; j < 8; j++) sum[j] += res[j];
            }
        }
    }
    if (d_cur >= 0) {
        float* p = agg + (long long)d_cur * DD + tx * 4;
        asm volatile("red.global.add.v4.f32 [%0], {%1,%2,%3,%4};"
                     :: "l"(p), "f"(sum[0]), "f"(sum[1]), "f"(sum[2]), "f"(sum[3]) : "memory");
        asm volatile("red.global.add.v4.f32 [%0], {%1,%2,%3,%4};"
                     :: "l"(p + 64), "f"(sum[4]), "f"(sum[5]), "f"(sum[6]), "f"(sum[7]) : "memory");
    }
}

// ===========================================================================
// Fused 2-GEMM MLP (bf16 split-mma, M=64 tiles):
//   h1 = relu(A@W1+b1) kept in smem as bf16 hi/lo (split from fp32 regs),
//   out = act(h1@W2+b2); optionally also written to agg (next-layer seed).
// 512 threads, 16 warps: w&3 -> m16 tile, w>>2 -> n32 quarter. 2 CTAs/SM.
// RACE FIX (R16): barrier between stage-1 mma reads and epilogue-1 writes
// into S_AH/S_AL — warps sharing an m-tile read each other's rows.
// ===========================================================================
#define S_AH 0
#define S_AL 16384
#define S_WH 32768
#define S_WL 65536
#define S_B1 98304
#define S_B2 98816
#define S_TOTAL 99328

template <bool RELU2, bool WRITE_AGG>
__global__ void __launch_bounds__(512, 2)
mlp_pair(const float* __restrict__ A,
         const __nv_bfloat16* __restrict__ w1H, const __nv_bfloat16* __restrict__ w1L,
         const float* __restrict__ b1,
         const __nv_bfloat16* __restrict__ w2H, const __nv_bfloat16* __restrict__ w2L,
         const float* __restrict__ b2,
         float* __restrict__ out, float* __restrict__ agg, int M) {
    extern __shared__ char smem[];
    const uint32_t sb = smem_u32(smem);
    const int tid = threadIdx.x;
    const int row0 = blockIdx.x * 64;

    // ---- stage-1 loads: A convert + W1 copy + biases ----
    for (int idx = tid; idx < 64 * 32; idx += 512) {
        int m = idx >> 5;
        int k4 = idx & 31;
        float4 v = make_float4(0.f, 0.f, 0.f, 0.f);
        int gm = row0 + m;
        if (gm < M) v = ((const float4*)A)[(long long)gm * 32 + k4];
        uint32_t off = asw(m, k4 >> 1) + (k4 & 1) * 8;
        *(uint2*)(smem + S_AH + off) = make_uint2(packbf(v.x, v.y), packbf(v.z, v.w));
        *(uint2*)(smem + S_AL + off) = make_uint2(packbf(bflo(v.x), bflo(v.y)),
                                                  packbf(bflo(v.z), bflo(v.w)));
    }
    for (int idx = tid; idx < 128 * 16 * 2; idx += 512) {
        int half = idx >> 11;
        int q = idx & 2047;
        int n = q >> 4;
        int c = q & 15;
        const __nv_bfloat16* src = half ? w1L : w1H;
        uint4 v = *(const uint4*)((const char*)(src + n * 128) + c * 16);
        *(uint4*)(smem + (half ? S_WL : S_WH) + asw(n, c)) = v;
    }
    if (tid < 128) ((float*)(smem + S_B1))[tid] = b1[tid];
    else if (tid < 256) ((float*)(smem + S_B2))[tid - 128] = b2[tid - 128];
    __syncthreads();

    const int w = tid >> 5;
    const int lane = tid & 31;
    const int m0 = (w & 3) * 16;
    const int nbase = (w >> 2) * 32;
    const int ar = m0 + (lane & 15);
    const int ak = lane >> 4;
    const int br = (lane & 7) + ((lane >> 4) << 3);
    const int bk = (lane >> 3) & 1;
    const int g = lane >> 2;
    const int tig = lane & 3;

    float c[4][4];
#pragma unroll
    for (int j = 0; j < 4; j++)
#pragma unroll
        for (int q = 0; q < 4; q++) c[j][q] = 0.f;

    // ---- stage-1 mma ----
#pragma unroll
    for (int kc = 0; kc < 8; kc++) {
        uint32_t ah[4], al[4];
        uint32_t aaddr = asw(ar, kc * 2 + ak);
        LDSM_X4(ah, sb + S_AH + aaddr);
        LDSM_X4(al, sb + S_AL + aaddr);
#pragma unroll
        for (int jp = 0; jp < 2; jp++) {
            int nrow = nbase + jp * 16 + br;
            uint32_t baddr = asw(nrow, kc * 2 + bk);
            uint32_t bh[4], bl[4];
            LDSM_X4(bh, sb + S_WH + baddr);
            LDSM_X4(bl, sb + S_WL + baddr);
            mma16816(c[jp * 2],     ah, bh[0], bh[1]);
            mma16816(c[jp * 2],     ah, bl[0], bl[1]);
            mma16816(c[jp * 2],     al, bh[0], bh[1]);
            mma16816(c[jp * 2 + 1], ah, bh[2], bh[3]);
            mma16816(c[jp * 2 + 1], ah, bl[2], bl[3]);
            mma16816(c[jp * 2 + 1], al, bh[2], bh[3]);
        }
    }

    // RACE FIX: all stage-1 A reads must complete before h1 overwrites A tiles
    __syncthreads();

    // ---- epilogue 1: h1 = relu(c+b1) -> S_AH/S_AL (own rows only) ----
    {
        const float* bs = (const float*)(smem + S_B1);
        const int rl = m0 + g;        // local rows
        const int rh = rl + 8;
#pragma unroll
        for (int j = 0; j < 4; j++) {
            int n0 = nbase + j * 8 + tig * 2;
            float bb0 = bs[n0], bb1 = bs[n0 + 1];
            float v0 = fmaxf(c[j][0] + bb0, 0.f), v1 = fmaxf(c[j][1] + bb1, 0.f);
            float v2 = fmaxf(c[j][2] + bb0, 0.f), v3 = fmaxf(c[j][3] + bb1, 0.f);
            uint32_t offl = asw(rl, n0 >> 3) + (n0 & 7) * 2;
            uint32_t offh = asw(rh, n0 >> 3) + (n0 & 7) * 2;
            *(uint32_t*)(smem + S_AH + offl) = packbf(v0, v1);
            *(uint32_t*)(smem + S_AL + offl) = packbf(bflo(v0), bflo(v1));
            *(uint32_t*)(smem + S_AH + offh) = packbf(v2, v3);
            *(uint32_t*)(smem + S_AL + offh) = packbf(bflo(v2), bflo(v3));
        }
    }
    __syncthreads();

    // ---- load W2 tiles ----
    for (int idx = tid; idx < 128 * 16 * 2; idx += 512) {
        int half = idx >> 11;
        int q = idx & 2047;
        int n = q >> 4;
        int c2 = q & 15;
        const __nv_bfloat16* src = half ? w2L : w2H;
        uint4 v = *(const uint4*)((const char*)(src + n * 128) + c2 * 16);
        *(uint4*)(smem + (half ? S_WL : S_WH) + asw(n, c2)) = v;
    }
    __syncthreads();

#pragma unroll
    for (int j = 0; j < 4; j++)
#pragma unroll
        for (int q = 0; q < 4; q++) c[j][q] = 0.f;

    // ---- stage-2 mma ----
#pragma unroll
    for (int kc = 0; kc < 8; kc++) {
        uint32_t ah[4], al[4];
        uint32_t aaddr = asw(ar, kc * 2 + ak);
        LDSM_X4(ah, sb + S_AH + aaddr);
        LDSM_X4(al, sb + S_AL + aaddr);
#pragma unroll
        for (int jp = 0; jp < 2; jp++) {
            int nrow = nbase + jp * 16 + br;
            uint32_t baddr = asw(nrow, kc * 2 + bk);
            uint32_t bh[4], bl[4];
            LDSM_X4(bh, sb + S_WH + baddr);
            LDSM_X4(bl, sb + S_WL + baddr);
            mma16816(c[jp * 2],     ah, bh[0], bh[1]);
            mma16816(c[jp * 2],     ah, bl[0], bl[1]);
            mma16816(c[jp * 2],     al, bh[0], bh[1]);
            mma16816(c[jp * 2 + 1], ah, bh[2], bh[3]);
            mma16816(c[jp * 2 + 1], ah, bl[2], bl[3]);
            mma16816(c[jp * 2 + 1], al, bh[2], bh[3]);
        }
    }

    // ---- epilogue 2: out (+ optional agg seed) ----
    {
        const float* bs = (const float*)(smem + S_B2);
        const int rlo = row0 + m0 + g;
        const int rhi = rlo + 8;
#pragma unroll
        for (int j = 0; j < 4; j++) {
            int n0 = nbase + j * 8 + tig * 2;
            float bb0 = bs[n0], bb1 = bs[n0 + 1];
            float v0 = c[j][0] + bb0, v1 = c[j][1] + bb1;
            float v2 = c[j][2] + bb0, v3 = c[j][3] + bb1;
            if (RELU2) {
                v0 = fmaxf(v0, 0.f); v1 = fmaxf(v1, 0.f);
                v2 = fmaxf(v2, 0.f); v3 = fmaxf(v3, 0.f);
            }
            if (rlo < M) {
                *(float2*)(out + (long long)rlo * DD + n0) = make_float2(v0, v1);
                if (WRITE_AGG)
                    *(float2*)(agg + (long long)rlo * DD + n0) = make_float2(v0, v1);
            }
            if (rhi < M) {
                *(float2*)(out + (long long)rhi * DD + n0) = make_float2(v2, v3);
                if (WRITE_AGG)
                    *(float2*)(agg + (long long)rhi * DD + n0) = make_float2(v2, v3);
            }
        }
    }
}

// ---------------------------------------------------------------------------
extern "C" void kernel_launch(void* const* d_in, const int* in_sizes, int n_in,
                              void* d_out, int out_size) {
    const float* x    = (const float*)d_in[0];
    const int*   ei   = (const int*)d_in[1];      // int32
    const float* ea   = (const float*)d_in[2];
    const float* w1_0 = (const float*)d_in[3];
    const float* b1_0 = (const float*)d_in[4];
    const float* w2_0 = (const float*)d_in[5];
    const float* b2_0 = (const float*)d_in[6];
    const float* we_0 = (const float*)d_in[7];
    const float* be_0 = (const float*)d_in[8];
    const float* w1_1 = (const float*)d_in[9];
    const float* b1_1 = (const float*)d_in[10];
    const float* w2_1 = (const float*)d_in[11];
    const float* b2_1 = (const float*)d_in[12];
    const float* we_1 = (const float*)d_in[13];
    const float* be_1 = (const float*)d_in[14];
    const float* fc1w = (const float*)d_in[15];
    const float* fc1b = (const float*)d_in[16];
    const float* fc2w = (const float*)d_in[17];
    const float* fc2b = (const float*)d_in[18];
    float* out = (float*)d_out;

    float *agg, *h;
    cudaGetSymbolAddress((void**)&agg, g_agg);
    cudaGetSymbolAddress((void**)&h,   g_h);
    __nv_bfloat16 *wtH, *wtL, *weH, *weL;
    cudaGetSymbolAddress((void**)&wtH, g_wtH);
    cudaGetSymbolAddress((void**)&wtL, g_wtL);
    cudaGetSymbolAddress((void**)&weH, g_weH);
    cudaGetSymbolAddress((void**)&weL, g_weL);

    cudaFuncSetAttribute(mlp_pair<true, true>,   cudaFuncAttributeMaxDynamicSharedMemorySize, S_TOTAL);
    cudaFuncSetAttribute(mlp_pair<true, false>,  cudaFuncAttributeMaxDynamicSharedMemorySize, S_TOTAL);
    cudaFuncSetAttribute(mlp_pair<false, false>, cudaFuncAttributeMaxDynamicSharedMemorySize, S_TOTAL);
    cudaFuncSetAttribute(edge_fused_kernel, cudaFuncAttributeMaxDynamicSharedMemorySize, E_TOTAL);

    const int n4 = NN * (DD / 4);
    const int copyBlocks = (n4 + 255) / 256;
    const int prepBlocks = (26624 + NN + 255) / 256;  // 300
    const int edgeThreadBlocks = (NE + 255) / 256;
    const int convEaBlocks = (int)(((long long)NE * 4 + 255) / 256);
    const int fusedBlocks = (NE + 127) / 128;         // 4688
    const int tcBlocks = (NN + 63) / 64;              // 782

    // ---- prep: weights + zero cnt (1 launch) ----
    prep_kernel<<<prepBlocks, 256>>>(w1_0, w2_0, w1_1, w2_1, fc1w, fc2w, we_0, we_1);

    // ---- CSR build ----
    hist_kernel<<<edgeThreadBlocks, 256>>>(ei);
    scan_kernel<<<1, 1024>>>();
    scatter_kernel<<<edgeThreadBlocks, 256>>>(ei);
    conv_ea_kernel<<<convEaBlocks, 256>>>((const float4*)ea);

    // ---- Layer 0 ----
    copy4_kernel<<<copyBlocks, 256>>>((const float4*)x, (float4*)agg, n4);
    edge_fused_kernel<<<fusedBlocks, 256, E_TOTAL>>>(x, weH, weL, be_0, agg);
    // h = MLP0(agg); also seeds agg = h for layer 1
    mlp_pair<true, true><<<tcBlocks, 512, S_TOTAL>>>(
        agg, wtH + 0 * DD * DD, wtL + 0 * DD * DD, b1_0,
             wtH + 1 * DD * DD, wtL + 1 * DD * DD, b2_0, h, agg, NN);

    // ---- Layer 1 ----
    edge_fused_kernel<<<fusedBlocks, 256, E_TOTAL>>>(h, weH + DD * DE, weL + DD * DE, be_1, agg);
    mlp_pair<true, false><<<tcBlocks, 512, S_TOTAL>>>(
        agg, wtH + 2 * DD * DD, wtL + 2 * DD * DD, b1_1,
             wtH + 3 * DD * DD, wtL + 3 * DD * DD, b2_1, h, nullptr, NN);

    // ---- Head ----
    mlp_pair<false, false><<<tcBlocks, 512, S_TOTAL>>>(
        h, wtH + 4 * DD * DD, wtL + 4 * DD * DD, fc1b,
           wtH + 5 * DD * DD, wtL + 5 * DD * DD, fc2b, out, nullptr, NN);
}